// round 14
// baseline (speedup 1.0000x reference)
#include <cuda_runtime.h>
#include <cstdint>
#include <math.h>

static constexpr int N_ROWS = 16384;
static constexpr int C_COLS = 1000;
static constexpr int C_CHUNK8 = C_COLS / 8;   // 125 32-byte chunks per row
static constexpr int WARPS_PER_BLOCK = 8;
static constexpr int THREADS = WARPS_PER_BLOCK * 32;      // 256
static constexpr int ROW_BLOCKS = N_ROWS / WARPS_PER_BLOCK; // 2048
static constexpr int GRID = ROW_BLOCKS + 1;               // +1 producer block

__device__ float  g_alpha[C_COLS];
__device__ double g_acc;
__device__ int    g_done  = 0;
__device__ int    g_ready = 0;

// 32-byte global load (v8.b32) — best-measured load shape for this kernel.
__device__ __forceinline__ void ldg8(const float* p, float v[8]) {
    asm volatile(
        "ld.global.nc.L2::evict_last.v8.b32 {%0,%1,%2,%3,%4,%5,%6,%7}, [%8];"
        : "=f"(v[0]), "=f"(v[1]), "=f"(v[2]), "=f"(v[3]),
          "=f"(v[4]), "=f"(v[5]), "=f"(v[6]), "=f"(v[7])
        : "l"(p));
}

__global__ __launch_bounds__(THREADS)
void fused_kernel(const float* __restrict__ feature,
                  const int* __restrict__ label,
                  float* __restrict__ out) {
    const int tid  = threadIdx.x;
    const int lane = tid & 31;
    const int wid  = tid >> 5;

    __shared__ int   sh_counts[C_COLS];       // used by producer block only
    __shared__ float warp_part[WARPS_PER_BLOCK];

    if (blockIdx.x == 0) {
        // ---------------- Producer block: histogram -> alpha table ----------
        for (int i = tid; i < C_COLS; i += THREADS) sh_counts[i] = 0;
        __syncthreads();

        const int4* lp = reinterpret_cast<const int4*>(label);
        for (int i = tid; i < N_ROWS / 4; i += THREADS) {
            int4 l4 = lp[i];
            if (l4.x >= 0 && l4.x < C_COLS) atomicAdd(&sh_counts[l4.x], 1);
            if (l4.y >= 0 && l4.y < C_COLS) atomicAdd(&sh_counts[l4.y], 1);
            if (l4.z >= 0 && l4.z < C_COLS) atomicAdd(&sh_counts[l4.z], 1);
            if (l4.w >= 0 && l4.w < C_COLS) atomicAdd(&sh_counts[l4.w], 1);
        }
        __syncthreads();

        for (int c = tid; c < C_COLS; c += THREADS) {
            float ni = (float)sh_counts[c];
            float r  = ni * (1.0f / (float)N_ROWS);
            g_alpha[c] = (ni > 0.0f) ? (__expf(r - 1.0f) / r) : 0.0f;
        }
        __syncthreads();
        if (tid == 0) {
            __threadfence();                               // publish g_alpha
            asm volatile("st.global.release.gpu.u32 [%0], %1;"
                         :: "l"(&g_ready), "r"(1) : "memory");
        }
    } else {
        // ---------------- Row blocks: one warp per row ----------------------
        const int row = (blockIdx.x - 1) * WARPS_PER_BLOCK + wid;

        // Lane 0 issues label/logit loads early; latency hides under the pass.
        int   l  = 0;
        float xl = 0.0f;
        if (lane == 0) {
            l = label[row];
            if (l < 0) l = 0;
            if (l >= C_COLS) l = C_COLS - 1;
            xl = feature[(size_t)row * C_COLS + l];
        }

        const float* rbase = feature + (size_t)row * C_COLS;
        float s = 0.0f;
        #pragma unroll
        for (int k = 0; k < 4; k++) {
            int idx = lane + k * 32;              // valid when < 125
            if (idx < C_CHUNK8) {
                float v[8];
                ldg8(rbase + idx * 8, v);
                s += __expf(v[0]) + __expf(v[1]) + __expf(v[2]) + __expf(v[3])
                   + __expf(v[4]) + __expf(v[5]) + __expf(v[6]) + __expf(v[7]);
            }
        }
        #pragma unroll
        for (int o = 16; o > 0; o >>= 1)
            s += __shfl_xor_sync(0xFFFFFFFFu, s, o);

        if (lane == 0) {
            // Wait for alpha table (producer is bid 0 -> wave 1; expected ~0 wait).
            unsigned int ready;
            do {
                asm volatile("ld.global.acquire.gpu.u32 %0, [%1];"
                             : "=r"(ready) : "l"(&g_ready) : "memory");
                if (!ready) __nanosleep(64);
            } while (!ready);
            float al;
            asm volatile("ld.global.cg.f32 %0, [%1];"
                         : "=f"(al) : "l"(&g_alpha[l]) : "memory");

            float logp = xl - __logf(s);
            float p    = __expf(logp);
            float omp  = 1.0f - p;
            warp_part[wid] = al * omp * omp * logp;
        }
        __syncthreads();

        if (tid == 0) {
            float blk = 0.0f;
            #pragma unroll
            for (int w = 0; w < WARPS_PER_BLOCK; w++) blk += warp_part[w];
            atomicAdd(&g_acc, (double)blk);
        }
    }

    // ---------------- Generic ticket: last of all 2049 blocks finishes ------
    __syncthreads();
    if (tid == 0) {
        __threadfence();
        int prev = atomicAdd(&g_done, 1);
        if (prev == (int)gridDim.x - 1) {
            double tot = atomicAdd(&g_acc, 0.0);   // coherent read of final sum
            out[0] = (float)(-tot / (double)N_ROWS);
            g_acc  = 0.0;                          // replay-safe reset
            g_ready = 0;
            __threadfence();
            g_done = 0;
        }
    }
}

extern "C" void kernel_launch(void* const* d_in, const int* in_sizes, int n_in,
                              void* d_out, int out_size) {
    const float* feature = (const float*)d_in[0];
    const int*   label   = (const int*)d_in[1];
    float*       out     = (float*)d_out;

    fused_kernel<<<GRID, THREADS>>>(feature, label, out);
}

// round 15
// speedup vs baseline: 1.5439x; 1.5439x over previous
#include <cuda_runtime.h>
#include <cstdint>
#include <math.h>

static constexpr int N_ROWS = 16384;
static constexpr int C_COLS = 1000;
static constexpr int C_CHUNK8 = C_COLS / 8;   // 125 32-byte chunks per row
static constexpr int WARPS_PER_BLOCK = 8;
static constexpr int THREADS = WARPS_PER_BLOCK * 32;      // 256
static constexpr int GRID = N_ROWS / WARPS_PER_BLOCK;     // 2048

__device__ int    g_cnt[C_COLS];     // zero-init at load; reset by finisher
__device__ double g_csum[C_COLS];    // per-class sum of beta*logp
__device__ int    g_done = 0;

// 32-byte global load (v8.b32) — best-measured load shape for this kernel.
__device__ __forceinline__ void ldg8(const float* p, float v[8]) {
    asm volatile(
        "ld.global.nc.L2::evict_last.v8.b32 {%0,%1,%2,%3,%4,%5,%6,%7}, [%8];"
        : "=f"(v[0]), "=f"(v[1]), "=f"(v[2]), "=f"(v[3]),
          "=f"(v[4]), "=f"(v[5]), "=f"(v[6]), "=f"(v[7])
        : "l"(p));
}

__global__ __launch_bounds__(THREADS, 8)
void row_kernel(const float* __restrict__ feature,
                const int* __restrict__ label,
                float* __restrict__ out) {
    const int tid  = threadIdx.x;
    const int lane = tid & 31;
    const int wid  = tid >> 5;
    const int row  = blockIdx.x * WARPS_PER_BLOCK + wid;

    __shared__ int    sh_last;
    __shared__ double sh_dwarp[WARPS_PER_BLOCK];

    // Lane 0 issues label/logit loads early; latency hides under the pass.
    int   l  = 0;
    float xl = 0.0f;
    if (lane == 0) {
        l = label[row];
        if (l < 0) l = 0;
        if (l >= C_COLS) l = C_COLS - 1;
        xl = feature[(size_t)row * C_COLS + l];
    }

    const float* rbase = feature + (size_t)row * C_COLS;
    float s = 0.0f;
    #pragma unroll
    for (int k = 0; k < 4; k++) {
        int idx = lane + k * 32;              // valid when < 125
        if (idx < C_CHUNK8) {
            float v[8];
            ldg8(rbase + idx * 8, v);
            s += __expf(v[0]) + __expf(v[1]) + __expf(v[2]) + __expf(v[3])
               + __expf(v[4]) + __expf(v[5]) + __expf(v[6]) + __expf(v[7]);
        }
    }
    #pragma unroll
    for (int o = 16; o > 0; o >>= 1)
        s += __shfl_xor_sync(0xFFFFFFFFu, s, o);

    if (lane == 0) {
        float logp = xl - __logf(s);
        float p    = __expf(logp);
        float omp  = 1.0f - p;
        // Class-separable: no alpha needed here. Two spread atomics.
        atomicAdd(&g_cnt[l], 1);
        atomicAdd(&g_csum[l], (double)(omp * omp * logp));
    }

    // ---------------- Ticket: last block does the class-space finish --------
    __syncthreads();
    if (tid == 0) {
        __threadfence();
        int prev = atomicAdd(&g_done, 1);
        sh_last = (prev == (int)gridDim.x - 1) ? 1 : 0;
        if (sh_last) __threadfence();
    }
    __syncthreads();

    if (sh_last) {
        // 1000 classes over 256 threads: alpha_c * S_c, then block reduce.
        double acc = 0.0;
        for (int c = tid; c < C_COLS; c += THREADS) {
            int ni = g_cnt[c];                       // atomics live in L2
            if (ni > 0) {
                float r  = (float)ni * (1.0f / (float)N_ROWS);
                float al = __expf(r - 1.0f) / r;
                acc += (double)al * __ldcg(&g_csum[c]);
            }
            // reset for next graph replay
            g_cnt[c]  = 0;
            g_csum[c] = 0.0;
        }
        #pragma unroll
        for (int o = 16; o > 0; o >>= 1)
            acc += __shfl_xor_sync(0xFFFFFFFFu, acc, o);
        if (lane == 0) sh_dwarp[wid] = acc;
        __syncthreads();
        if (tid == 0) {
            double tot = 0.0;
            #pragma unroll
            for (int w = 0; w < WARPS_PER_BLOCK; w++) tot += sh_dwarp[w];
            out[0] = (float)(-tot / (double)N_ROWS);
            __threadfence();
            g_done = 0;                              // replay-safe reset
        }
    }
}

extern "C" void kernel_launch(void* const* d_in, const int* in_sizes, int n_in,
                              void* d_out, int out_size) {
    const float* feature = (const float*)d_in[0];
    const int*   label   = (const int*)d_in[1];
    float*       out     = (float*)d_out;

    row_kernel<<<GRID, THREADS>>>(feature, label, out);
}

// round 16
// speedup vs baseline: 1.5644x; 1.0133x over previous
#include <cuda_runtime.h>
#include <cstdint>
#include <math.h>

static constexpr int N_ROWS = 16384;
static constexpr int C_COLS = 1000;
static constexpr int C_VEC  = C_COLS / 4;      // 250 float4 per row
static constexpr int THREADS = 1024;           // 32 warps = full SM
static constexpr int GRID_ROW = 148;           // oe = 1 CTA per SM, one wave
static constexpr int GW = GRID_ROW * (THREADS / 32);   // 4736 warps

__device__ float  g_alpha[C_COLS];
__device__ double g_acc;
__device__ int    g_done = 0;

// ---------------------------------------------------------------------------
// Kernel 1: one block builds label histogram -> alpha[] table; resets state.
// ---------------------------------------------------------------------------
__global__ __launch_bounds__(1024)
void alpha_kernel(const int* __restrict__ label) {
    __shared__ int sh_counts[C_COLS];

    for (int i = threadIdx.x; i < C_COLS; i += 1024) sh_counts[i] = 0;
    if (threadIdx.x == 0) { g_acc = 0.0; g_done = 0; }
    __syncthreads();

    const int4* lp = reinterpret_cast<const int4*>(label);
    for (int i = threadIdx.x; i < N_ROWS / 4; i += 1024) {
        int4 l4 = lp[i];
        if (l4.x >= 0 && l4.x < C_COLS) atomicAdd(&sh_counts[l4.x], 1);
        if (l4.y >= 0 && l4.y < C_COLS) atomicAdd(&sh_counts[l4.y], 1);
        if (l4.z >= 0 && l4.z < C_COLS) atomicAdd(&sh_counts[l4.z], 1);
        if (l4.w >= 0 && l4.w < C_COLS) atomicAdd(&sh_counts[l4.w], 1);
    }
    __syncthreads();

    for (int c = threadIdx.x; c < C_COLS; c += 1024) {
        float ni = (float)sh_counts[c];
        float r  = ni * (1.0f / (float)N_ROWS);
        g_alpha[c] = (ni > 0.0f) ? (__expf(r - 1.0f) / r) : 0.0f;
    }
}

// ---------------------------------------------------------------------------
// Kernel 2: oe=1 — one 1024-thread CTA per SM; each warp grid-strides rows
// with the proven streaming body. Collapses the cross-CTA L1tex-queue spread
// to its floor while keeping per-SM in-flight bytes far above the BW*latency
// requirement.
// ---------------------------------------------------------------------------
__global__ __launch_bounds__(THREADS, 1)
void row_kernel(const float* __restrict__ feature,
                const int* __restrict__ label,
                float* __restrict__ out) {
    const int tid  = threadIdx.x;
    const int lane = tid & 31;
    const int wid  = tid >> 5;
    const int gw   = blockIdx.x * (THREADS / 32) + wid;   // 0..4735

    __shared__ double sh_dwarp[THREADS / 32];
    __shared__ int    sh_last;

    double acc = 0.0;

    for (int row = gw; row < N_ROWS; row += GW) {
        // Lane 0 issues label/logit/alpha loads first; latency hides under pass.
        float xl = 0.0f, al = 0.0f;
        if (lane == 0) {
            int l = label[row];
            if (l < 0) l = 0;
            if (l >= C_COLS) l = C_COLS - 1;
            xl = feature[(size_t)row * C_COLS + l];
            al = g_alpha[l];
        }

        const float4* rp =
            reinterpret_cast<const float4*>(feature + (size_t)row * C_COLS);
        float s = 0.0f;
        #pragma unroll
        for (int k = 0; k < 8; k++) {
            int idx = lane + k * 32;
            if (idx < C_VEC) {
                float4 v = rp[idx];
                s += __expf(v.x) + __expf(v.y) + __expf(v.z) + __expf(v.w);
            }
        }
        #pragma unroll
        for (int o = 16; o > 0; o >>= 1)
            s += __shfl_xor_sync(0xFFFFFFFFu, s, o);

        if (lane == 0) {
            float logp = xl - __logf(s);
            float p    = __expf(logp);
            float omp  = 1.0f - p;
            acc += (double)(al * omp * omp * logp);
        }
    }

    if (lane == 0) sh_dwarp[wid] = acc;
    __syncthreads();

    // Warp 0 reduces the 32 per-warp partials; one atomic per block (148 total).
    if (wid == 0) {
        double a = sh_dwarp[lane];
        #pragma unroll
        for (int o = 16; o > 0; o >>= 1)
            a += __shfl_xor_sync(0xFFFFFFFFu, a, o);
        if (lane == 0) atomicAdd(&g_acc, a);
    }
    __syncthreads();

    if (tid == 0) {
        __threadfence();
        int prev = atomicAdd(&g_done, 1);
        sh_last = (prev == (int)gridDim.x - 1) ? 1 : 0;
    }
    __syncthreads();

    if (sh_last && tid == 0) {
        double tot = atomicAdd(&g_acc, 0.0);   // coherent read of final sum
        out[0] = (float)(-tot / (double)N_ROWS);
        g_done = 0;                            // replay-safe reset
    }
}

extern "C" void kernel_launch(void* const* d_in, const int* in_sizes, int n_in,
                              void* d_out, int out_size) {
    const float* feature = (const float*)d_in[0];
    const int*   label   = (const int*)d_in[1];
    float*       out     = (float*)d_out;

    alpha_kernel<<<1, 1024>>>(label);
    row_kernel<<<GRID_ROW, THREADS>>>(feature, label, out);
}

// round 17
// speedup vs baseline: 1.7066x; 1.0909x over previous
#include <cuda_runtime.h>
#include <math.h>

static constexpr int N_ROWS = 16384;
static constexpr int C_COLS = 1000;
static constexpr int C_VEC  = C_COLS / 4;     // 250 float4 per row
static constexpr int WARPS_PER_BLOCK = 8;
static constexpr int THREADS = WARPS_PER_BLOCK * 32;     // 256
static constexpr int GRID    = N_ROWS / WARPS_PER_BLOCK; // 2048

__device__ float  g_alpha[C_COLS];
__device__ double g_acc;
__device__ int    g_done = 0;

// ---------------------------------------------------------------------------
// Kernel 1: one block builds the label histogram and the alpha[] table,
// and resets the accumulator/ticket for this replay.
// ---------------------------------------------------------------------------
__global__ __launch_bounds__(1024)
void alpha_kernel(const int* __restrict__ label) {
    __shared__ int sh_counts[C_COLS];

    for (int i = threadIdx.x; i < C_COLS; i += 1024) sh_counts[i] = 0;
    if (threadIdx.x == 0) { g_acc = 0.0; g_done = 0; }
    __syncthreads();

    const int4* lp = reinterpret_cast<const int4*>(label);
    for (int i = threadIdx.x; i < N_ROWS / 4; i += 1024) {
        int4 l4 = lp[i];
        if (l4.x >= 0 && l4.x < C_COLS) atomicAdd(&sh_counts[l4.x], 1);
        if (l4.y >= 0 && l4.y < C_COLS) atomicAdd(&sh_counts[l4.y], 1);
        if (l4.z >= 0 && l4.z < C_COLS) atomicAdd(&sh_counts[l4.z], 1);
        if (l4.w >= 0 && l4.w < C_COLS) atomicAdd(&sh_counts[l4.w], 1);
    }
    __syncthreads();

    for (int c = threadIdx.x; c < C_COLS; c += 1024) {
        float ni = (float)sh_counts[c];
        float r  = ni * (1.0f / (float)N_ROWS);
        g_alpha[c] = (ni > 0.0f) ? (__expf(r - 1.0f) / r) : 0.0f;
    }
}

// ---------------------------------------------------------------------------
// Kernel 2: one warp per row, single streaming pass (no max subtraction —
// inputs are O(1) logits, exp() cannot overflow). Minimal register footprint.
// ---------------------------------------------------------------------------
__global__ __launch_bounds__(THREADS)
void row_kernel(const float* __restrict__ feature,
                const int* __restrict__ label,
                float* __restrict__ out) {
    const int warp_id = threadIdx.x >> 5;
    const int lane    = threadIdx.x & 31;
    const int row     = blockIdx.x * WARPS_PER_BLOCK + warp_id;

    __shared__ float warp_part[WARPS_PER_BLOCK];

    // Lane 0 issues the label + gathered-logit loads early so their latency
    // hides under the streaming pass below.
    int   l  = 0;
    float xl = 0.0f;
    float al = 0.0f;
    if (lane == 0) {
        l = label[row];
        if (l < 0) l = 0;
        if (l >= C_COLS) l = C_COLS - 1;
        xl = feature[(size_t)row * C_COLS + l];
        al = g_alpha[l];
    }

    const float4* rp =
        reinterpret_cast<const float4*>(feature + (size_t)row * C_COLS);

    float s = 0.0f;
    #pragma unroll
    for (int k = 0; k < 8; k++) {
        int idx = lane + k * 32;
        if (idx < C_VEC) {
            float4 v = rp[idx];
            s += __expf(v.x) + __expf(v.y) + __expf(v.z) + __expf(v.w);
        }
    }
    #pragma unroll
    for (int o = 16; o > 0; o >>= 1)
        s += __shfl_xor_sync(0xFFFFFFFFu, s, o);

    if (lane == 0) {
        float logp = xl - __logf(s);
        float p    = __expf(logp);
        float omp  = 1.0f - p;
        warp_part[warp_id] = al * omp * omp * logp;
    }
    __syncthreads();

    if (threadIdx.x == 0) {
        float blk = 0.0f;
        #pragma unroll
        for (int w = 0; w < WARPS_PER_BLOCK; w++) blk += warp_part[w];
        atomicAdd(&g_acc, (double)blk);
        __threadfence();
        int prev = atomicAdd(&g_done, 1);
        if (prev == (int)gridDim.x - 1) {
            double tot = atomicAdd(&g_acc, 0.0);   // coherent read of final sum
            out[0] = (float)(-tot / (double)N_ROWS);
            g_done = 0;                            // replay-safe reset
        }
    }
}

extern "C" void kernel_launch(void* const* d_in, const int* in_sizes, int n_in,
                              void* d_out, int out_size) {
    const float* feature = (const float*)d_in[0];
    const int*   label   = (const int*)d_in[1];
    float*       out     = (float*)d_out;

    alpha_kernel<<<1, 1024>>>(label);
    row_kernel<<<GRID, THREADS>>>(feature, label, out);
}